// round 1
// baseline (speedup 1.0000x reference)
#include <cuda_runtime.h>
#include <math.h>

#define BATCH 128
#define TLEN  1024
#define NCH   64

// Scratch ping-pong activation buffers (B, 64, T) each = 32 MB. bss, no allocation.
static __device__ float g_h[BATCH * NCH * TLEN];
static __device__ float g_f[BATCH * NCH * TLEN];

// ---------------------------------------------------------------------------
// Causal dilated conv: out[b,o,t] = act( bias[o] + sum_{i,k} w[o,i,k] * in[b,i,t-(K-1-k)*d] )
// Thread tile: 8 outputs (o) x 4 time points (t = t0 + lane + 32*tt).
// GUARD instantiation handles the zero left-padding (only the t0==0 tile).
// XIN: input is the virtual concat [x (15ch) ; fveg_emb[fveg_ids[b]] (8ch, t-const)].
// ---------------------------------------------------------------------------
template <int CI, int KK, int D, bool XIN, bool GUARD>
__device__ __forceinline__ void conv_main(
    const float* __restrict__ inb, const float* __restrict__ embrow,
    const float* __restrict__ w_s, int t0, int tg, int obase,
    float (&acc)[8][4])
{
#pragma unroll 2
    for (int i = 0; i < CI; i++) {
        const bool isemb = XIN && (i >= 15);
        const float* xrow = inb + i * TLEN;
        float ev = 0.f;
        if (isemb) ev = __ldg(embrow + (i - 15));
#pragma unroll
        for (int k = 0; k < KK; k++) {
            float wv[8];
#pragma unroll
            for (int oo = 0; oo < 8; oo++)
                wv[oo] = w_s[((obase + oo) * CI + i) * KK + k];  // warp-broadcast LDS

            const int toff = (KK - 1 - k) * D;
            float xv[4];
#pragma unroll
            for (int tt = 0; tt < 4; tt++) {
                int t = t0 + tg + 32 * tt - toff;
                float v;
                if (isemb) {
                    v = (!GUARD || t >= 0) ? ev : 0.f;
                } else {
                    v = (!GUARD || t >= 0) ? __ldg(xrow + t) : 0.f;  // coalesced over lanes
                }
                xv[tt] = v;
            }
#pragma unroll
            for (int oo = 0; oo < 8; oo++)
#pragma unroll
                for (int tt = 0; tt < 4; tt++)
                    acc[oo][tt] = fmaf(wv[oo], xv[tt], acc[oo][tt]);
        }
    }
}

template <int CI, int KK, int D, bool RELU, bool ACC, bool XIN>
__global__ void __launch_bounds__(256) conv_kernel(
    const float* __restrict__ in,   // (B, 15, T) if XIN else (B, CI, T)
    const int*   __restrict__ ids,  // (B,)       [XIN only]
    const float* __restrict__ emb,  // (32, 8)    [XIN only]
    const float* __restrict__ w,    // (64, CI, KK)
    const float* __restrict__ bias, // (64,)
    float* __restrict__ out)        // (B, 64, T)
{
    __shared__ float w_s[NCH * CI * KK];   // <= 48 KB (64*64*3*4 = 49152 exactly)
    const int t0  = blockIdx.x * 128;
    const int b   = blockIdx.y;
    const int tid = threadIdx.x;

    for (int m = tid; m < NCH * CI * KK; m += 256) w_s[m] = w[m];  // coalesced both sides
    __syncthreads();

    const int tg    = tid & 31;
    const int obase = (tid >> 5) * 8;
    const float* inb = in + (size_t)b * (XIN ? 15 : CI) * TLEN;
    const float* embrow = XIN ? (emb + (size_t)__ldg(ids + b) * 8) : (const float*)nullptr;

    float acc[8][4];
#pragma unroll
    for (int oo = 0; oo < 8; oo++)
#pragma unroll
        for (int tt = 0; tt < 4; tt++) acc[oo][tt] = 0.f;

    if (t0 == 0)
        conv_main<CI, KK, D, XIN, true >(inb, embrow, w_s, t0, tg, obase, acc);
    else
        conv_main<CI, KK, D, XIN, false>(inb, embrow, w_s, t0, tg, obase, acc);

#pragma unroll
    for (int oo = 0; oo < 8; oo++) {
        float bv = __ldg(bias + obase + oo);
        float* orow = out + ((size_t)b * NCH + obase + oo) * TLEN + t0 + tg;
#pragma unroll
        for (int tt = 0; tt < 4; tt++) {
            float v = acc[oo][tt] + bv;
            if (RELU) v = fmaxf(v, 0.f);
            if (ACC)  v += orow[32 * tt];
            orow[32 * tt] = v;
        }
    }
}

// ---------------------------------------------------------------------------
// Heads: pet = softplus(<pet_w,f>+b), pck likewise,
//        aet = sigmoid(<aet_w[0:64],f> + aet_w[64]*pet + aet_w[65]*pck + b) * pet,
//        cwd = pet - aet.   Output layout: [pet | pck | aet | cwd], each (B,1,T).
// ---------------------------------------------------------------------------
__device__ __forceinline__ float softplusf(float x) {
    if (x > 20.f) return x;
    return log1pf(expf(x));
}

__global__ void __launch_bounds__(256) head_kernel(
    const float* __restrict__ f,
    const float* __restrict__ pet_w, const float* __restrict__ pet_b,
    const float* __restrict__ pck_w, const float* __restrict__ pck_b,
    const float* __restrict__ aet_w, const float* __restrict__ aet_b,
    float* __restrict__ out)
{
    int g = blockIdx.x * blockDim.x + threadIdx.x;
    if (g >= BATCH * TLEN) return;
    const int b = g / TLEN;
    const int t = g % TLEN;
    const float* fb = f + (size_t)b * NCH * TLEN + t;

    float a0 = 0.f, a1 = 0.f, a2 = 0.f;
#pragma unroll 4
    for (int c = 0; c < NCH; c++) {
        float v = __ldg(fb + c * TLEN);         // coalesced over lanes (t)
        a0 = fmaf(__ldg(pet_w + c), v, a0);
        a1 = fmaf(__ldg(pck_w + c), v, a1);
        a2 = fmaf(__ldg(aet_w + c), v, a2);
    }
    float pet = softplusf(a0 + __ldg(pet_b));
    float pck = softplusf(a1 + __ldg(pck_b));
    float z   = a2 + __ldg(aet_w + 64) * pet + __ldg(aet_w + 65) * pck + __ldg(aet_b);
    float aet = pet / (1.f + expf(-z));
    float cwd = pet - aet;

    const int N = BATCH * TLEN;
    out[g]         = pet;
    out[N + g]     = pck;
    out[2 * N + g] = aet;
    out[3 * N + g] = cwd;
}

// ---------------------------------------------------------------------------
extern "C" void kernel_launch(void* const* d_in, const int* in_sizes, int n_in,
                              void* d_out, int out_size)
{
    const float* x     = (const float*)d_in[0];
    const int*   ids   = (const int*)  d_in[1];
    const float* emb   = (const float*)d_in[2];
    const float* w0a   = (const float*)d_in[3];
    const float* b0a   = (const float*)d_in[4];
    const float* w0b   = (const float*)d_in[5];
    const float* b0b   = (const float*)d_in[6];
    const float* w0r   = (const float*)d_in[7];
    const float* b0r   = (const float*)d_in[8];
    const float* wa    = (const float*)d_in[9];
    const float* ba    = (const float*)d_in[10];
    const float* wb    = (const float*)d_in[11];
    const float* bb    = (const float*)d_in[12];
    const float* pet_w = (const float*)d_in[13];
    const float* pet_b = (const float*)d_in[14];
    const float* pck_w = (const float*)d_in[15];
    const float* pck_b = (const float*)d_in[16];
    const float* aet_w = (const float*)d_in[17];
    const float* aet_b = (const float*)d_in[18];
    float* out = (float*)d_out;

    float *h, *f;
    cudaGetSymbolAddress((void**)&h, g_h);
    cudaGetSymbolAddress((void**)&f, g_f);

    dim3 grid(TLEN / 128, BATCH);
    dim3 blk(256);
    const int WSTRIDE = NCH * NCH * 3;   // 12288 floats per wa[i]/wb[i]

    // Block 0 (d=1): h = relu(conv3(xin, w0a)); f = conv1(xin, w0r); f += relu(conv3(h, w0b))
    conv_kernel<23, 3, 1, true,  false, true ><<<grid, blk>>>(x, ids, emb, w0a, b0a, h);
    conv_kernel<23, 1, 1, false, false, true ><<<grid, blk>>>(x, ids, emb, w0r, b0r, f);
    conv_kernel<64, 3, 1, true,  true,  false><<<grid, blk>>>(h, nullptr, nullptr, w0b, b0b, f);

    // Residual blocks, d = 2, 4, 8, 16
    conv_kernel<64, 3, 2,  true, false, false><<<grid, blk>>>(f, nullptr, nullptr, wa + 0 * WSTRIDE, ba + 0 * NCH, h);
    conv_kernel<64, 3, 2,  true, true,  false><<<grid, blk>>>(h, nullptr, nullptr, wb + 0 * WSTRIDE, bb + 0 * NCH, f);

    conv_kernel<64, 3, 4,  true, false, false><<<grid, blk>>>(f, nullptr, nullptr, wa + 1 * WSTRIDE, ba + 1 * NCH, h);
    conv_kernel<64, 3, 4,  true, true,  false><<<grid, blk>>>(h, nullptr, nullptr, wb + 1 * WSTRIDE, bb + 1 * NCH, f);

    conv_kernel<64, 3, 8,  true, false, false><<<grid, blk>>>(f, nullptr, nullptr, wa + 2 * WSTRIDE, ba + 2 * NCH, h);
    conv_kernel<64, 3, 8,  true, true,  false><<<grid, blk>>>(h, nullptr, nullptr, wb + 2 * WSTRIDE, bb + 2 * NCH, f);

    conv_kernel<64, 3, 16, true, false, false><<<grid, blk>>>(f, nullptr, nullptr, wa + 3 * WSTRIDE, ba + 3 * NCH, h);
    conv_kernel<64, 3, 16, true, true,  false><<<grid, blk>>>(h, nullptr, nullptr, wb + 3 * WSTRIDE, bb + 3 * NCH, f);

    // Heads
    head_kernel<<<(BATCH * TLEN + 255) / 256, blk>>>(f, pet_w, pet_b, pck_w, pck_b,
                                                     aet_w, aet_b, out);
}

// round 3
// speedup vs baseline: 2.0114x; 2.0114x over previous
#include <cuda_runtime.h>
#include <math.h>
#include <stdint.h>

#define BATCH 128
#define TLEN  1024
#define NCH   64

// Scratch ping-pong activation buffers (B, 64, T) each = 32 MB. bss, no allocation.
static __device__ float g_h[BATCH * NCH * TLEN];
static __device__ float g_f[BATCH * NCH * TLEN];

// ---------------------------------------------------------------------------
// tf32 helpers (baseline PTX, valid on target sm_100)
// ---------------------------------------------------------------------------
__device__ __forceinline__ uint32_t tf32r(float f) {
    uint32_t r;
    asm("cvt.rna.tf32.f32 %0, %1;" : "=r"(r) : "f"(f));
    return r;
}

__device__ __forceinline__ void mma_tf32(float (&d)[4],
                                         uint32_t a0, uint32_t a1, uint32_t a2, uint32_t a3,
                                         uint32_t b0, uint32_t b1) {
    asm volatile(
        "mma.sync.aligned.m16n8k8.row.col.f32.tf32.tf32.f32 "
        "{%0,%1,%2,%3}, {%4,%5,%6,%7}, {%8,%9}, {%0,%1,%2,%3};"
        : "+f"(d[0]), "+f"(d[1]), "+f"(d[2]), "+f"(d[3])
        : "r"(a0), "r"(a1), "r"(a2), "r"(a3), "r"(b0), "r"(b1));
}

// ---------------------------------------------------------------------------
// Tensor-core (mma.sync tf32) causal dilated conv, 64->64, K=3:
//   out[b,o,t] = relu(bias[o] + sum_{i,k} w[o,i,k] * in[b,i,t-(2-k)d])   (+= out if ACC)
// CTA = (batch b, 128-t tile). M=128 t-rows, N=64 o, K = 64 ch x 3 taps.
// smem A: halo-staged tile, rows t0-2D..t0+127 at stride 68 (conflict-free frag reads).
// smem B: per-tap weights [o][i] at stride 68 (conflict-free frag reads).
// Epilogue bounces through smem (stride 65) for coalesced global stores.
// ---------------------------------------------------------------------------
#define ASTR 68
#define BSTR 68
#define CSTR 65
#define A_ROWS_MAX 160                       // 128 + 2*16
#define SM_A_FLOATS (A_ROWS_MAX * ASTR)      // 10880
#define SM_B_FLOATS (3 * NCH * BSTR)         // 13056
#define MCONV_SMEM  ((SM_A_FLOATS + SM_B_FLOATS) * 4)   // 95744 B

template <int D, bool ACC>
__global__ void __launch_bounds__(256) mconv_kernel(
    const float* __restrict__ in,   // (B, 64, T)
    const float* __restrict__ w,    // (64, 64, 3)
    const float* __restrict__ bias, // (64,)
    float* __restrict__ out)        // (B, 64, T)
{
    extern __shared__ float smem[];
    float* As = smem;                  // A tile (also reused as C in epilogue)
    float* Bs = smem + SM_A_FLOATS;
    uint32_t* Au = (uint32_t*)As;
    uint32_t* Bu = (uint32_t*)Bs;

    const int tid = threadIdx.x;
    const int t0  = blockIdx.x * 128;
    const int b   = blockIdx.y;
    constexpr int NR = 128 + 2 * D;    // staged rows (with causal halo)

    // ---- stage A: rows = t0-2D .. t0+127, tf32-rounded; coalesced over t ----
    const float* inb = in + (size_t)b * NCH * TLEN;
    for (int idx = tid; idx < NCH * NR; idx += 256) {
        const int ch  = idx / NR;
        const int row = idx - ch * NR;
        const int t   = t0 + row - 2 * D;
        float v = (t >= 0) ? __ldg(inb + ch * TLEN + t) : 0.f;
        Au[row * ASTR + ch] = tf32r(v);
    }

    // ---- stage B: w(o,i,k) -> Bs[k][o*BSTR + i], tf32-rounded; coalesced read ----
    for (int idx = tid; idx < NCH * NCH * 3; idx += 256) {
        const int o   = idx / 192;
        const int rem = idx - o * 192;
        const int i   = rem / 3;
        const int k   = rem - 3 * i;
        Bu[(k * NCH + o) * BSTR + i] = tf32r(__ldg(w + idx));
    }
    __syncthreads();

    // ---- mma main loop: warp = 16 t-rows x 64 o ----
    const int wid  = tid >> 5;
    const int lane = tid & 31;
    const int g    = lane >> 2;     // group id (0..7)
    const int tg   = lane & 3;      // thread in group (0..3)
    const int mrow = wid * 16;

    float acc[8][4];
#pragma unroll
    for (int nt = 0; nt < 8; nt++)
#pragma unroll
        for (int r = 0; r < 4; r++) acc[nt][r] = 0.f;

#pragma unroll
    for (int k = 0; k < 3; k++) {
        const uint32_t* Atap = Au + (k * D + mrow) * ASTR;   // frag rows rel. to here
        const uint32_t* Btap = Bu + (k * NCH) * BSTR;
#pragma unroll
        for (int kc = 0; kc < 8; kc++) {
            const int c0 = kc * 8 + tg;
            uint32_t a0 = Atap[(g)      * ASTR + c0];
            uint32_t a1 = Atap[(g + 8)  * ASTR + c0];
            uint32_t a2 = Atap[(g)      * ASTR + c0 + 4];
            uint32_t a3 = Atap[(g + 8)  * ASTR + c0 + 4];
#pragma unroll
            for (int nt = 0; nt < 8; nt++) {
                const uint32_t* brow = Btap + (nt * 8 + g) * BSTR + kc * 8 + tg;
                mma_tf32(acc[nt], a0, a1, a2, a3, brow[0], brow[4]);
            }
        }
    }

    // ---- epilogue: acc -> smem C (stride 65) -> coalesced global ----
    __syncthreads();   // everyone done reading As before we overwrite it
    float* Cs = As;
#pragma unroll
    for (int nt = 0; nt < 8; nt++) {
        const int col = nt * 8 + tg * 2;
        Cs[(mrow + g)     * CSTR + col]     = acc[nt][0];
        Cs[(mrow + g)     * CSTR + col + 1] = acc[nt][1];
        Cs[(mrow + g + 8) * CSTR + col]     = acc[nt][2];
        Cs[(mrow + g + 8) * CSTR + col + 1] = acc[nt][3];
    }
    __syncthreads();

    const int tl    = tid & 127;        // t within tile
    const int ohalf = tid >> 7;         // 0 or 1
    float* ob = out + (size_t)b * NCH * TLEN + t0 + tl;
#pragma unroll 8
    for (int oo = 0; oo < 32; oo++) {
        const int o = ohalf * 32 + oo;
        float v = Cs[tl * CSTR + o] + __ldg(bias + o);
        v = fmaxf(v, 0.f);
        if (ACC) v += ob[o * TLEN];
        ob[o * TLEN] = v;
    }
}

// ===========================================================================
// CUDA-core conv for the 23-ch layer-0 kernels
// ===========================================================================
template <int CI, int KK, int D, bool XIN, bool GUARD>
__device__ __forceinline__ void conv_main(
    const float* __restrict__ inb, const float* __restrict__ embrow,
    const float* __restrict__ w_s, int t0, int tg, int obase,
    float (&acc)[8][4])
{
#pragma unroll 2
    for (int i = 0; i < CI; i++) {
        const bool isemb = XIN && (i >= 15);
        const float* xrow = inb + i * TLEN;
        float ev = 0.f;
        if (isemb) ev = __ldg(embrow + (i - 15));
#pragma unroll
        for (int k = 0; k < KK; k++) {
            float wv[8];
#pragma unroll
            for (int oo = 0; oo < 8; oo++)
                wv[oo] = w_s[((obase + oo) * CI + i) * KK + k];
            const int toff = (KK - 1 - k) * D;
            float xv[4];
#pragma unroll
            for (int tt = 0; tt < 4; tt++) {
                int t = t0 + tg + 32 * tt - toff;
                float v;
                if (isemb) v = (!GUARD || t >= 0) ? ev : 0.f;
                else       v = (!GUARD || t >= 0) ? __ldg(xrow + t) : 0.f;
                xv[tt] = v;
            }
#pragma unroll
            for (int oo = 0; oo < 8; oo++)
#pragma unroll
                for (int tt = 0; tt < 4; tt++)
                    acc[oo][tt] = fmaf(wv[oo], xv[tt], acc[oo][tt]);
        }
    }
}

template <int CI, int KK, int D, bool RELU, bool ACC, bool XIN>
__global__ void __launch_bounds__(256) conv_kernel(
    const float* __restrict__ in, const int* __restrict__ ids,
    const float* __restrict__ emb, const float* __restrict__ w,
    const float* __restrict__ bias, float* __restrict__ out)
{
    __shared__ float w_s[NCH * CI * KK];
    const int t0  = blockIdx.x * 128;
    const int b   = blockIdx.y;
    const int tid = threadIdx.x;

    for (int m = tid; m < NCH * CI * KK; m += 256) w_s[m] = w[m];
    __syncthreads();

    const int tg    = tid & 31;
    const int obase = (tid >> 5) * 8;
    const float* inb = in + (size_t)b * (XIN ? 15 : CI) * TLEN;
    const float* embrow = XIN ? (emb + (size_t)__ldg(ids + b) * 8) : (const float*)nullptr;

    float acc[8][4];
#pragma unroll
    for (int oo = 0; oo < 8; oo++)
#pragma unroll
        for (int tt = 0; tt < 4; tt++) acc[oo][tt] = 0.f;

    if (t0 == 0) conv_main<CI, KK, D, XIN, true >(inb, embrow, w_s, t0, tg, obase, acc);
    else         conv_main<CI, KK, D, XIN, false>(inb, embrow, w_s, t0, tg, obase, acc);

#pragma unroll
    for (int oo = 0; oo < 8; oo++) {
        float bv = __ldg(bias + obase + oo);
        float* orow = out + ((size_t)b * NCH + obase + oo) * TLEN + t0 + tg;
#pragma unroll
        for (int tt = 0; tt < 4; tt++) {
            float v = acc[oo][tt] + bv;
            if (RELU) v = fmaxf(v, 0.f);
            if (ACC)  v += orow[32 * tt];
            orow[32 * tt] = v;
        }
    }
}

// ===========================================================================
// Heads
// ===========================================================================
__device__ __forceinline__ float softplusf(float x) {
    if (x > 20.f) return x;
    return log1pf(expf(x));
}

__global__ void __launch_bounds__(256) head_kernel(
    const float* __restrict__ f,
    const float* __restrict__ pet_w, const float* __restrict__ pet_b,
    const float* __restrict__ pck_w, const float* __restrict__ pck_b,
    const float* __restrict__ aet_w, const float* __restrict__ aet_b,
    float* __restrict__ out)
{
    int g = blockIdx.x * blockDim.x + threadIdx.x;
    if (g >= BATCH * TLEN) return;
    const int b = g / TLEN;
    const int t = g % TLEN;
    const float* fb = f + (size_t)b * NCH * TLEN + t;

    float a0 = 0.f, a1 = 0.f, a2 = 0.f;
#pragma unroll 4
    for (int c = 0; c < NCH; c++) {
        float v = __ldg(fb + c * TLEN);
        a0 = fmaf(__ldg(pet_w + c), v, a0);
        a1 = fmaf(__ldg(pck_w + c), v, a1);
        a2 = fmaf(__ldg(aet_w + c), v, a2);
    }
    float pet = softplusf(a0 + __ldg(pet_b));
    float pck = softplusf(a1 + __ldg(pck_b));
    float z   = a2 + __ldg(aet_w + 64) * pet + __ldg(aet_w + 65) * pck + __ldg(aet_b);
    float aet = pet / (1.f + expf(-z));
    float cwd = pet - aet;

    const int N = BATCH * TLEN;
    out[g]         = pet;
    out[N + g]     = pck;
    out[2 * N + g] = aet;
    out[3 * N + g] = cwd;
}

// ===========================================================================
extern "C" void kernel_launch(void* const* d_in, const int* in_sizes, int n_in,
                              void* d_out, int out_size)
{
    const float* x     = (const float*)d_in[0];
    const int*   ids   = (const int*)  d_in[1];
    const float* emb   = (const float*)d_in[2];
    const float* w0a   = (const float*)d_in[3];
    const float* b0a   = (const float*)d_in[4];
    const float* w0b   = (const float*)d_in[5];
    const float* b0b   = (const float*)d_in[6];
    const float* w0r   = (const float*)d_in[7];
    const float* b0r   = (const float*)d_in[8];
    const float* wa    = (const float*)d_in[9];
    const float* ba    = (const float*)d_in[10];
    const float* wb    = (const float*)d_in[11];
    const float* bb    = (const float*)d_in[12];
    const float* pet_w = (const float*)d_in[13];
    const float* pet_b = (const float*)d_in[14];
    const float* pck_w = (const float*)d_in[15];
    const float* pck_b = (const float*)d_in[16];
    const float* aet_w = (const float*)d_in[17];
    const float* aet_b = (const float*)d_in[18];
    float* out = (float*)d_out;

    float *h, *f;
    cudaGetSymbolAddress((void**)&h, g_h);
    cudaGetSymbolAddress((void**)&f, g_f);

    cudaFuncSetAttribute(mconv_kernel<1,  true >, cudaFuncAttributeMaxDynamicSharedMemorySize, MCONV_SMEM);
    cudaFuncSetAttribute(mconv_kernel<2,  false>, cudaFuncAttributeMaxDynamicSharedMemorySize, MCONV_SMEM);
    cudaFuncSetAttribute(mconv_kernel<2,  true >, cudaFuncAttributeMaxDynamicSharedMemorySize, MCONV_SMEM);
    cudaFuncSetAttribute(mconv_kernel<4,  false>, cudaFuncAttributeMaxDynamicSharedMemorySize, MCONV_SMEM);
    cudaFuncSetAttribute(mconv_kernel<4,  true >, cudaFuncAttributeMaxDynamicSharedMemorySize, MCONV_SMEM);
    cudaFuncSetAttribute(mconv_kernel<8,  false>, cudaFuncAttributeMaxDynamicSharedMemorySize, MCONV_SMEM);
    cudaFuncSetAttribute(mconv_kernel<8,  true >, cudaFuncAttributeMaxDynamicSharedMemorySize, MCONV_SMEM);
    cudaFuncSetAttribute(mconv_kernel<16, false>, cudaFuncAttributeMaxDynamicSharedMemorySize, MCONV_SMEM);
    cudaFuncSetAttribute(mconv_kernel<16, true >, cudaFuncAttributeMaxDynamicSharedMemorySize, MCONV_SMEM);

    dim3 grid(TLEN / 128, BATCH);
    const int WSTRIDE = NCH * NCH * 3;

    // Block 0 (d=1): h = relu(conv3(xin, w0a)); f = conv1(xin, w0r); f += relu(conv3(h, w0b))
    conv_kernel<23, 3, 1, true,  false, true ><<<grid, 256>>>(x, ids, emb, w0a, b0a, h);
    conv_kernel<23, 1, 1, false, false, true ><<<grid, 256>>>(x, ids, emb, w0r, b0r, f);
    mconv_kernel<1,  true ><<<grid, 256, MCONV_SMEM>>>(h, w0b, b0b, f);

    // Residual blocks, d = 2, 4, 8, 16 (tensor cores via mma.sync tf32)
    mconv_kernel<2,  false><<<grid, 256, MCONV_SMEM>>>(f, wa + 0 * WSTRIDE, ba + 0 * NCH, h);
    mconv_kernel<2,  true ><<<grid, 256, MCONV_SMEM>>>(h, wb + 0 * WSTRIDE, bb + 0 * NCH, f);

    mconv_kernel<4,  false><<<grid, 256, MCONV_SMEM>>>(f, wa + 1 * WSTRIDE, ba + 1 * NCH, h);
    mconv_kernel<4,  true ><<<grid, 256, MCONV_SMEM>>>(h, wb + 1 * WSTRIDE, bb + 1 * NCH, f);

    mconv_kernel<8,  false><<<grid, 256, MCONV_SMEM>>>(f, wa + 2 * WSTRIDE, ba + 2 * NCH, h);
    mconv_kernel<8,  true ><<<grid, 256, MCONV_SMEM>>>(h, wb + 2 * WSTRIDE, bb + 2 * NCH, f);

    mconv_kernel<16, false><<<grid, 256, MCONV_SMEM>>>(f, wa + 3 * WSTRIDE, ba + 3 * NCH, h);
    mconv_kernel<16, true ><<<grid, 256, MCONV_SMEM>>>(h, wb + 3 * WSTRIDE, bb + 3 * NCH, f);

    // Heads
    head_kernel<<<(BATCH * TLEN + 255) / 256, 256>>>(f, pet_w, pet_b, pck_w, pck_b,
                                                     aet_w, aet_b, out);
}

// round 4
// speedup vs baseline: 2.1142x; 1.0511x over previous
#include <cuda_runtime.h>
#include <math.h>
#include <stdint.h>

#define BATCH 128
#define TLEN  1024
#define NCH   64

// Channels-last (B, T, 64) activation ping-pong buffers. bss, no allocation.
static __device__ float g_h[BATCH * TLEN * NCH];
static __device__ float g_f[BATCH * TLEN * NCH];
// Repacked tf32 weight fragments: 9 sets x 6144 uint2 (b0,b1 pairs).
static __device__ uint2 g_wp[9 * 6144];

// ---------------------------------------------------------------------------
// helpers
// ---------------------------------------------------------------------------
__device__ __forceinline__ uint32_t tf32r(float f) {
    uint32_t r;
    asm("cvt.rna.tf32.f32 %0, %1;" : "=r"(r) : "f"(f));
    return r;
}
__device__ __forceinline__ uint32_t smem_u32(const void* p) {
    uint32_t a;
    asm("{ .reg .u64 t; cvta.to.shared.u64 t, %1; cvt.u32.u64 %0, t; }" : "=r"(a) : "l"(p));
    return a;
}
__device__ __forceinline__ void mma_tf32(float (&d)[4],
                                         uint32_t a0, uint32_t a1, uint32_t a2, uint32_t a3,
                                         uint32_t b0, uint32_t b1) {
    asm volatile(
        "mma.sync.aligned.m16n8k8.row.col.f32.tf32.tf32.f32 "
        "{%0,%1,%2,%3}, {%4,%5,%6,%7}, {%8,%9}, {%0,%1,%2,%3};"
        : "+f"(d[0]), "+f"(d[1]), "+f"(d[2]), "+f"(d[3])
        : "r"(a0), "r"(a1), "r"(a2), "r"(a3), "r"(b0), "r"(b1));
}
#define LDSM4(r, a) \
    asm volatile("ldmatrix.sync.aligned.m8n8.x4.shared.b16 {%0,%1,%2,%3}, [%4];" \
        : "=r"((r)[0]), "=r"((r)[1]), "=r"((r)[2]), "=r"((r)[3]) : "r"(a))

// ---------------------------------------------------------------------------
// Weight repack: w(o,i,k) fp32 -> per-set uint2 frag pairs, tf32-rounded.
// Layout: wp[set][ ((k*8+kc)*64 + o)*4 + tg ] = { w[o][kc*8+tg][k], w[o][kc*8+tg+4][k] }
// Sets: 0 = w0b, 1..4 = wa[0..3], 5..8 = wb[0..3].
// ---------------------------------------------------------------------------
__global__ void repack_kernel(const float* __restrict__ w0b,
                              const float* __restrict__ wa,
                              const float* __restrict__ wb) {
    int i = blockIdx.x * 256 + threadIdx.x;
    if (i >= 9 * 6144) return;
    int s  = i / 6144, r = i - s * 6144;
    int tg = r & 3;
    int t1 = r >> 2;
    int o  = t1 & 63;
    int kk = t1 >> 6;          // 0..23
    int k  = kk >> 3, kc = kk & 7;
    const float* src = (s == 0) ? w0b : (s <= 4 ? wa + (s - 1) * 12288 : wb + (s - 5) * 12288);
    int i0 = kc * 8 + tg;
    uint2 v;
    v.x = tf32r(__ldg(src + (o * 64 + i0) * 3 + k));
    v.y = tf32r(__ldg(src + (o * 64 + i0 + 4) * 3 + k));
    g_wp[i] = v;
}

// ---------------------------------------------------------------------------
// Tensor-core causal dilated conv 64->64 K=3 (channels-last activations):
//   out[b,t,o] = relu(bias[o] + sum_{i,k} w[o,i,k] * in[b, t-(2-k)D, i])  (+= out if ACC)
// CTA = (128-t tile, batch). 8 warps in 4(M) x 2(N) grid; warp = 32t x 32o.
// A smem: rows t0-2D .. t0+127 at stride 68 floats (ldmatrix conflict-free).
// B: direct LDG.64 of prepacked frags (L1/L2-hot, identical across CTAs).
// ---------------------------------------------------------------------------
template <int D, bool ACC>
__global__ void __launch_bounds__(256, 4) mconv_kernel(
    const float* __restrict__ in,   // (B, T, 64)
    const uint2* __restrict__ wp,   // 6144 frag pairs
    const float* __restrict__ bias, // (64,)
    float* __restrict__ out)        // (B, T, 64)
{
    extern __shared__ float smem[];
    constexpr int NR = 128 + 2 * D;
    const int tid = threadIdx.x;
    const int t0  = blockIdx.x * 128;
    const int b   = blockIdx.y;

    // ---- stage A: NR rows x 64 ch, vectorized, tf32-rounded ----
    const float* ibase = in + ((size_t)b * TLEN + t0 - 2 * D) * 64;
    for (int idx = tid; idx < NR * 16; idx += 256) {
        const int r = idx >> 4, c4 = idx & 15;
        float4 v = make_float4(0.f, 0.f, 0.f, 0.f);
        if (t0 - 2 * D + r >= 0)
            v = __ldg((const float4*)(ibase + (size_t)r * 64) + c4);
        uint4 u;
        u.x = tf32r(v.x); u.y = tf32r(v.y); u.z = tf32r(v.z); u.w = tf32r(v.w);
        *(uint4*)(smem + r * 68 + c4 * 4) = u;
    }
    __syncthreads();

    const int lane  = tid & 31, wid = tid >> 5;
    const int warpM = wid & 3,  warpN = wid >> 2;
    const int g     = lane >> 2, tg = lane & 3;

    // ldmatrix per-lane address (rows for 4 sub-matrices of the x4)
    const uint32_t a_lane = smem_u32(smem) +
        (((warpM * 32 + (lane & 15)) * 68) + ((lane >> 4) << 2)) * 4;
    const uint2* wl = wp + (warpN * 32 + g) * 4 + tg;

    float acc[2][4][4];
#pragma unroll
    for (int mf = 0; mf < 2; mf++)
#pragma unroll
        for (int nf = 0; nf < 4; nf++)
#pragma unroll
            for (int r = 0; r < 4; r++) acc[mf][nf][r] = 0.f;

#pragma unroll
    for (int k = 0; k < 3; k++) {
#pragma unroll
        for (int kc = 0; kc < 8; kc++) {
            uint32_t A0[4], A1[4];
            const uint32_t ad = a_lane + (k * D) * 272 + kc * 32;
            LDSM4(A0, ad);
            LDSM4(A1, ad + 16 * 272);
            const uint2* wk = wl + (k * 8 + kc) * 256;
            const uint2 b0 = __ldg(wk);
            const uint2 b1 = __ldg(wk + 32);
            const uint2 b2 = __ldg(wk + 64);
            const uint2 b3 = __ldg(wk + 96);
            mma_tf32(acc[0][0], A0[0], A0[1], A0[2], A0[3], b0.x, b0.y);
            mma_tf32(acc[0][1], A0[0], A0[1], A0[2], A0[3], b1.x, b1.y);
            mma_tf32(acc[0][2], A0[0], A0[1], A0[2], A0[3], b2.x, b2.y);
            mma_tf32(acc[0][3], A0[0], A0[1], A0[2], A0[3], b3.x, b3.y);
            mma_tf32(acc[1][0], A1[0], A1[1], A1[2], A1[3], b0.x, b0.y);
            mma_tf32(acc[1][1], A1[0], A1[1], A1[2], A1[3], b1.x, b1.y);
            mma_tf32(acc[1][2], A1[0], A1[1], A1[2], A1[3], b2.x, b2.y);
            mma_tf32(acc[1][3], A1[0], A1[1], A1[2], A1[3], b3.x, b3.y);
        }
    }

    // ---- epilogue: bounce through smem (stride 66 / half-offset 33) ----
    __syncthreads();   // A reads complete; reuse smem as C
#pragma unroll
    for (int mf = 0; mf < 2; mf++)
#pragma unroll
        for (int nf = 0; nf < 4; nf++) {
            const int ro = warpM * 32 + mf * 16 + g;
            const int co = warpN * 33 + nf * 8 + tg * 2;
            smem[ro * 66 + co]           = acc[mf][nf][0];
            smem[ro * 66 + co + 1]       = acc[mf][nf][1];
            smem[(ro + 8) * 66 + co]     = acc[mf][nf][2];
            smem[(ro + 8) * 66 + co + 1] = acc[mf][nf][3];
        }
    __syncthreads();

    const int tl = tid >> 1, h2 = tid & 1;
    float* orow = out + ((size_t)b * TLEN + t0 + tl) * 64 + h2 * 32;
    const float* crow = smem + tl * 66 + h2 * 33;
#pragma unroll
    for (int j = 0; j < 8; j++) {
        const float4 bv = __ldg((const float4*)bias + h2 * 8 + j);
        float4 v;
        v.x = fmaxf(crow[j * 4 + 0] + bv.x, 0.f);
        v.y = fmaxf(crow[j * 4 + 1] + bv.y, 0.f);
        v.z = fmaxf(crow[j * 4 + 2] + bv.z, 0.f);
        v.w = fmaxf(crow[j * 4 + 3] + bv.w, 0.f);
        if (ACC) {
            const float4 rr = __ldg((const float4*)orow + j);
            v.x += rr.x; v.y += rr.y; v.z += rr.z; v.w += rr.w;
        }
        ((float4*)orow)[j] = v;
    }
}

// ===========================================================================
// CUDA-core layer-0 convs (23-ch input, x t-major; OUTPUT channels-last)
// ===========================================================================
template <int CI, int KK, bool GUARD>
__device__ __forceinline__ void conv0_main(
    const float* __restrict__ inb, const float* __restrict__ embrow,
    const float* __restrict__ w_s, int t0, int tg, int obase,
    float (&acc)[8][4])
{
#pragma unroll 2
    for (int i = 0; i < CI; i++) {
        const bool isemb = (i >= 15);
        const float* xrow = inb + i * TLEN;
        float ev = 0.f;
        if (isemb) ev = __ldg(embrow + (i - 15));
#pragma unroll
        for (int k = 0; k < KK; k++) {
            float wv[8];
#pragma unroll
            for (int oo = 0; oo < 8; oo++)
                wv[oo] = w_s[((obase + oo) * CI + i) * KK + k];
            const int toff = (KK - 1 - k);
            float xv[4];
#pragma unroll
            for (int tt = 0; tt < 4; tt++) {
                int t = t0 + tg + 32 * tt - toff;
                float v;
                if (isemb) v = (!GUARD || t >= 0) ? ev : 0.f;
                else       v = (!GUARD || t >= 0) ? __ldg(xrow + t) : 0.f;
                xv[tt] = v;
            }
#pragma unroll
            for (int oo = 0; oo < 8; oo++)
#pragma unroll
                for (int tt = 0; tt < 4; tt++)
                    acc[oo][tt] = fmaf(wv[oo], xv[tt], acc[oo][tt]);
        }
    }
}

template <int CI, int KK, bool RELU>
__global__ void __launch_bounds__(256) conv0_kernel(
    const float* __restrict__ x, const int* __restrict__ ids,
    const float* __restrict__ emb, const float* __restrict__ w,
    const float* __restrict__ bias, float* __restrict__ out)  // out (B,T,64)
{
    extern __shared__ float sm[];
    float* w_s = sm;                        // CI*KK*64 floats
    float* cs  = sm + CI * KK * 64;         // 128*66 + 33 + 31 bounce
    const int t0  = blockIdx.x * 128;
    const int b   = blockIdx.y;
    const int tid = threadIdx.x;

    for (int m = tid; m < NCH * CI * KK; m += 256) w_s[m] = w[m];
    __syncthreads();

    const int tg    = tid & 31;
    const int obase = (tid >> 5) * 8;
    const float* inb = x + (size_t)b * 15 * TLEN;
    const float* embrow = emb + (size_t)__ldg(ids + b) * 8;

    float acc[8][4];
#pragma unroll
    for (int oo = 0; oo < 8; oo++)
#pragma unroll
        for (int tt = 0; tt < 4; tt++) acc[oo][tt] = 0.f;

    if (t0 == 0) conv0_main<CI, KK, true >(inb, embrow, w_s, t0, tg, obase, acc);
    else         conv0_main<CI, KK, false>(inb, embrow, w_s, t0, tg, obase, acc);

    // bounce to channels-last
    const int half = obase >> 5, ob = obase & 31;
#pragma unroll
    for (int oo = 0; oo < 8; oo++) {
        const float bv = __ldg(bias + obase + oo);
#pragma unroll
        for (int tt = 0; tt < 4; tt++) {
            float v = acc[oo][tt] + bv;
            if (RELU) v = fmaxf(v, 0.f);
            cs[(tg + 32 * tt) * 66 + half * 33 + ob + oo] = v;
        }
    }
    __syncthreads();

    const int tl = tid >> 1, h2 = tid & 1;
    float* orow = out + ((size_t)b * TLEN + t0 + tl) * 64 + h2 * 32;
    const float* crow = cs + tl * 66 + h2 * 33;
#pragma unroll
    for (int j = 0; j < 8; j++) {
        float4 v;
        v.x = crow[j * 4 + 0]; v.y = crow[j * 4 + 1];
        v.z = crow[j * 4 + 2]; v.w = crow[j * 4 + 3];
        ((float4*)orow)[j] = v;
    }
}

// ===========================================================================
// Heads (f channels-last)
// ===========================================================================
__device__ __forceinline__ float softplusf(float x) {
    if (x > 20.f) return x;
    return log1pf(expf(x));
}

__global__ void __launch_bounds__(256) head_kernel(
    const float* __restrict__ f,
    const float* __restrict__ pet_w, const float* __restrict__ pet_b,
    const float* __restrict__ pck_w, const float* __restrict__ pck_b,
    const float* __restrict__ aet_w, const float* __restrict__ aet_b,
    float* __restrict__ out)
{
    int g = blockIdx.x * blockDim.x + threadIdx.x;
    if (g >= BATCH * TLEN) return;
    const float* fb = f + (size_t)g * 64;

    float a0 = 0.f, a1 = 0.f, a2 = 0.f;
#pragma unroll
    for (int j = 0; j < 16; j++) {
        const float4 v  = __ldg((const float4*)fb + j);
        const float4 w0 = __ldg((const float4*)pet_w + j);
        const float4 w1 = __ldg((const float4*)pck_w + j);
        const float4 w2 = __ldg((const float4*)aet_w + j);
        a0 += v.x * w0.x + v.y * w0.y + v.z * w0.z + v.w * w0.w;
        a1 += v.x * w1.x + v.y * w1.y + v.z * w1.z + v.w * w1.w;
        a2 += v.x * w2.x + v.y * w2.y + v.z * w2.z + v.w * w2.w;
    }
    float pet = softplusf(a0 + __ldg(pet_b));
    float pck = softplusf(a1 + __ldg(pck_b));
    float z   = a2 + __ldg(aet_w + 64) * pet + __ldg(aet_w + 65) * pck + __ldg(aet_b);
    float aet = pet / (1.f + expf(-z));
    float cwd = pet - aet;

    const int N = BATCH * TLEN;
    out[g]         = pet;
    out[N + g]     = pck;
    out[2 * N + g] = aet;
    out[3 * N + g] = cwd;
}

// ===========================================================================
extern "C" void kernel_launch(void* const* d_in, const int* in_sizes, int n_in,
                              void* d_out, int out_size)
{
    const float* x     = (const float*)d_in[0];
    const int*   ids   = (const int*)  d_in[1];
    const float* emb   = (const float*)d_in[2];
    const float* w0a   = (const float*)d_in[3];
    const float* b0a   = (const float*)d_in[4];
    const float* w0b   = (const float*)d_in[5];
    const float* b0b   = (const float*)d_in[6];
    const float* w0r   = (const float*)d_in[7];
    const float* b0r   = (const float*)d_in[8];
    const float* wa    = (const float*)d_in[9];
    const float* ba    = (const float*)d_in[10];
    const float* wb    = (const float*)d_in[11];
    const float* bb    = (const float*)d_in[12];
    const float* pet_w = (const float*)d_in[13];
    const float* pet_b = (const float*)d_in[14];
    const float* pck_w = (const float*)d_in[15];
    const float* pck_b = (const float*)d_in[16];
    const float* aet_w = (const float*)d_in[17];
    const float* aet_b = (const float*)d_in[18];
    float* out = (float*)d_out;

    float *h, *f;
    uint2* wp;
    cudaGetSymbolAddress((void**)&h, g_h);
    cudaGetSymbolAddress((void**)&f, g_f);
    cudaGetSymbolAddress((void**)&wp, g_wp);

    // dynamic smem sizes
    const int SM_C0K3 = (23 * 3 * 64 + 128 * 66 + 64) * 4;   // ~52 KB -> needs attr
    const int SM_C0K1 = (23 * 1 * 64 + 128 * 66 + 64) * 4;
    cudaFuncSetAttribute(conv0_kernel<23, 3, true >, cudaFuncAttributeMaxDynamicSharedMemorySize, SM_C0K3);
    cudaFuncSetAttribute(conv0_kernel<23, 1, false>, cudaFuncAttributeMaxDynamicSharedMemorySize, SM_C0K1);

    dim3 grid(TLEN / 128, BATCH);

    // Repack all 9 heavy-layer weight tensors into tf32 frag pairs.
    repack_kernel<<<(9 * 6144 + 255) / 256, 256>>>(w0b, wa, wb);

    // Block 0 (d=1): h = relu(conv3(xin, w0a)); f = conv1(xin, w0r); f += relu(conv3(h, w0b))
    conv0_kernel<23, 3, true ><<<grid, 256, SM_C0K3>>>(x, ids, emb, w0a, b0a, h);
    conv0_kernel<23, 1, false><<<grid, 256, SM_C0K1>>>(x, ids, emb, w0r, b0r, f);

    #define MCONV_SM(D) ((128 + 2 * (D)) * 68 * 4)
    mconv_kernel<1,  true ><<<grid, 256, MCONV_SM(1)>>>(h, wp + 0 * 6144, b0b, f);

    mconv_kernel<2,  false><<<grid, 256, MCONV_SM(2)>>>(f, wp + 1 * 6144, ba + 0 * NCH, h);
    mconv_kernel<2,  true ><<<grid, 256, MCONV_SM(2)>>>(h, wp + 5 * 6144, bb + 0 * NCH, f);

    mconv_kernel<4,  false><<<grid, 256, MCONV_SM(4)>>>(f, wp + 2 * 6144, ba + 1 * NCH, h);
    mconv_kernel<4,  true ><<<grid, 256, MCONV_SM(4)>>>(h, wp + 6 * 6144, bb + 1 * NCH, f);

    mconv_kernel<8,  false><<<grid, 256, MCONV_SM(8)>>>(f, wp + 3 * 6144, ba + 2 * NCH, h);
    mconv_kernel<8,  true ><<<grid, 256, MCONV_SM(8)>>>(h, wp + 7 * 6144, bb + 2 * NCH, f);

    mconv_kernel<16, false><<<grid, 256, MCONV_SM(16)>>>(f, wp + 4 * 6144, ba + 3 * NCH, h);
    mconv_kernel<16, true ><<<grid, 256, MCONV_SM(16)>>>(h, wp + 8 * 6144, bb + 3 * NCH, f);

    head_kernel<<<(BATCH * TLEN + 255) / 256, 256>>>(f, pet_w, pet_b, pck_w, pck_b,
                                                     aet_w, aet_b, out);
}

// round 5
// speedup vs baseline: 3.5941x; 1.7000x over previous
#include <cuda_runtime.h>
#include <cuda_fp16.h>
#include <math.h>
#include <stdint.h>

#define BATCH 128
#define TLEN  1024
#define NCH   64

// Activations: f (residual stream) fp32, h (conv intermediate) fp16. bss, no alloc.
static __device__ float  g_f[BATCH * TLEN * NCH];
static __device__ __half g_h[BATCH * TLEN * NCH];
// Repacked fp16 B-fragments: 9 heavy sets x 3072 + conv0 set x 3072 uint2.
static __device__ uint2  g_wp[10 * 3072];

// ---------------------------------------------------------------------------
// helpers
// ---------------------------------------------------------------------------
__device__ __forceinline__ uint32_t smem_u32(const void* p) {
    uint32_t a;
    asm("{ .reg .u64 t; cvta.to.shared.u64 t, %1; cvt.u32.u64 %0, t; }" : "=r"(a) : "l"(p));
    return a;
}
__device__ __forceinline__ uint32_t h2pack(float lo, float hi) {
    __half2 h = __floats2half2_rn(lo, hi);
    return *(uint32_t*)&h;
}
__device__ __forceinline__ void mma_f16(float (&d)[4], const uint32_t (&a)[4], uint2 b) {
    asm volatile(
        "mma.sync.aligned.m16n8k16.row.col.f32.f16.f16.f32 "
        "{%0,%1,%2,%3}, {%4,%5,%6,%7}, {%8,%9}, {%0,%1,%2,%3};"
        : "+f"(d[0]), "+f"(d[1]), "+f"(d[2]), "+f"(d[3])
        : "r"(a[0]), "r"(a[1]), "r"(a[2]), "r"(a[3]), "r"(b.x), "r"(b.y));
}
#define LDSM4(r, a) \
    asm volatile("ldmatrix.sync.aligned.m8n8.x4.shared.b16 {%0,%1,%2,%3}, [%4];" \
        : "=r"((r)[0]), "=r"((r)[1]), "=r"((r)[2]), "=r"((r)[3]) : "r"(a))

// ---------------------------------------------------------------------------
// Weight repack (fp16 B fragments for m16n8k16).
// Heavy set s (K=192 = 3 taps x 4 kc16 over 64 ch):
//   g_wp[s*3072 + (kk*8 + ob8)*32 + lane] =
//     { h2(w[o][i0],w[o][i0+1]), h2(w[o][i0+8],w[o][i0+9]) }   (tap from kk>>2)
//   with o = ob8*8 + lane/4, tg = lane&3, i0 = (kk&3)*16 + 2*tg.
// conv0 set (K=96 = 3 taps x 2 kc16 over 32 padded ch; N=128 = [w0a | w0r@tap2]):
// ---------------------------------------------------------------------------
__global__ void repack_kernel(const float* __restrict__ w0b,
                              const float* __restrict__ wa,
                              const float* __restrict__ wb,
                              const float* __restrict__ w0a,
                              const float* __restrict__ w0r) {
    const int i = blockIdx.x * 256 + threadIdx.x;
    if (i >= 10 * 3072) return;
    const int lane = i & 31, tg = lane & 3;
    uint2 v;
    if (i < 9 * 3072) {
        const int s = i / 3072, r = i - s * 3072;
        const int t1 = r >> 5, ob8 = t1 & 7, kk = t1 >> 3;
        const int tap = kk >> 2, cc = kk & 3;
        const int o = ob8 * 8 + ((r & 31) >> 2);
        const int i0 = cc * 16 + 2 * tg;
        const float* src = (s == 0) ? w0b : (s <= 4 ? wa + (s - 1) * 12288 : wb + (s - 5) * 12288);
        v.x = h2pack(__ldg(src + (o * 64 + i0) * 3 + tap),     __ldg(src + (o * 64 + i0 + 1) * 3 + tap));
        v.y = h2pack(__ldg(src + (o * 64 + i0 + 8) * 3 + tap), __ldg(src + (o * 64 + i0 + 9) * 3 + tap));
    } else {
        const int r = i - 9 * 3072;
        const int t1 = r >> 5, ob8 = t1 & 15, kk = t1 >> 4;
        const int tap = kk >> 1, cc = kk & 1;
        const int o = ob8 * 8 + ((r & 31) >> 2);
        const int i0 = cc * 16 + 2 * tg;
        float f[4];
#pragma unroll
        for (int j = 0; j < 4; j++) {
            const int ii = i0 + (j >> 1) * 8 + (j & 1);
            float w = 0.f;
            if (ii < 23) {
                if (o < 64)            w = __ldg(w0a + (o * 23 + ii) * 3 + tap);
                else if (tap == 2)     w = __ldg(w0r + (o - 64) * 23 + ii);
            }
            f[j] = w;
        }
        v.x = h2pack(f[0], f[1]);
        v.y = h2pack(f[2], f[3]);
    }
    g_wp[i] = v;
}

// ---------------------------------------------------------------------------
// Heavy conv 64->64 K=3, fp16 mma (m16n8k16), channels-last.
// IN_HALF=false: in = f (fp32), out = h (fp16, relu).
// IN_HALF=true : in = h (fp16), out = f (fp32, relu + residual add).
// CTA = (128-t tile, batch). 8 warps 4M x 2N; warp = 32t x 32o. K = 12 kc16.
// A smem: NR=128+2D rows x 64 fp16, row stride 144B (LDSM conflict-free).
// Epilogue bounce: fp32, row stride 72 words (conflict-free STS.64 + LDS.128).
// ---------------------------------------------------------------------------
#define MCONV_SMEM 36864   // 128*72*4 bounce (>= A region for D<=16)

template <int D, bool IN_HALF>
__global__ void __launch_bounds__(256, 4) mconv_kernel(
    const void* __restrict__ in_v,
    void* __restrict__ out_v,
    const uint2* __restrict__ wp,
    const float* __restrict__ bias)
{
    extern __shared__ __align__(16) char smraw[];
    float* smf = (float*)smraw;
    constexpr int NR = 128 + 2 * D;
    const int tid = threadIdx.x;
    const int t0  = blockIdx.x * 128;
    const int b   = blockIdx.y;

    // ---- stage A ----
    if (IN_HALF) {
        const __half* in = (const __half*)in_v;
        const __half* ib = in + ((size_t)b * TLEN + t0 - 2 * D) * 64;
        for (int idx = tid; idx < NR * 8; idx += 256) {
            const int r = idx >> 3, c8 = idx & 7;
            uint4 u = make_uint4(0, 0, 0, 0);
            if (t0 - 2 * D + r >= 0)
                u = __ldg((const uint4*)(ib + (size_t)r * 64) + c8);
            *(uint4*)(smraw + r * 144 + c8 * 16) = u;
        }
    } else {
        const float* in = (const float*)in_v;
        const float* ib = in + ((size_t)b * TLEN + t0 - 2 * D) * 64;
        for (int idx = tid; idx < NR * 16; idx += 256) {
            const int r = idx >> 4, c4 = idx & 15;
            float4 vv = make_float4(0.f, 0.f, 0.f, 0.f);
            if (t0 - 2 * D + r >= 0)
                vv = __ldg((const float4*)(ib + (size_t)r * 64) + c4);
            uint2 u;
            u.x = h2pack(vv.x, vv.y);
            u.y = h2pack(vv.z, vv.w);
            *(uint2*)(smraw + r * 144 + c4 * 8) = u;
        }
    }
    __syncthreads();

    const int lane = tid & 31, wid = tid >> 5;
    const int warpM = wid & 3, warpN = wid >> 2;
    const int g = lane >> 2, tg = lane & 3;

    const uint32_t a_base = smem_u32(smraw) +
        (warpM * 32 + (lane & 15)) * 144 + ((lane >> 4) << 4);
    const uint2* wl = wp + lane;

    float acc[2][4][4];
#pragma unroll
    for (int mf = 0; mf < 2; mf++)
#pragma unroll
        for (int nf = 0; nf < 4; nf++)
#pragma unroll
            for (int r = 0; r < 4; r++) acc[mf][nf][r] = 0.f;

#pragma unroll
    for (int k = 0; k < 3; k++) {
#pragma unroll
        for (int cc = 0; cc < 4; cc++) {
            uint32_t A0[4], A1[4];
            const uint32_t ad = a_base + k * (D * 144) + cc * 32;
            LDSM4(A0, ad);
            LDSM4(A1, ad + 16 * 144);
            const int kk = k * 4 + cc;
            const uint2* wk = wl + (kk * 8 + warpN * 4) * 32;
            const uint2 b0 = __ldg(wk);
            const uint2 b1 = __ldg(wk + 32);
            const uint2 b2 = __ldg(wk + 64);
            const uint2 b3 = __ldg(wk + 96);
            mma_f16(acc[0][0], A0, b0);
            mma_f16(acc[0][1], A0, b1);
            mma_f16(acc[0][2], A0, b2);
            mma_f16(acc[0][3], A0, b3);
            mma_f16(acc[1][0], A1, b0);
            mma_f16(acc[1][1], A1, b1);
            mma_f16(acc[1][2], A1, b2);
            mma_f16(acc[1][3], A1, b3);
        }
    }

    // ---- epilogue bounce (stride 72 words) ----
    __syncthreads();
#pragma unroll
    for (int mf = 0; mf < 2; mf++)
#pragma unroll
        for (int nf = 0; nf < 4; nf++) {
            const int ro = warpM * 32 + mf * 16 + g;
            const int co = warpN * 36 + nf * 8 + tg * 2;
            smf[ro * 72 + co]           = acc[mf][nf][0];
            smf[ro * 72 + co + 1]       = acc[mf][nf][1];
            smf[(ro + 8) * 72 + co]     = acc[mf][nf][2];
            smf[(ro + 8) * 72 + co + 1] = acc[mf][nf][3];
        }
    __syncthreads();

    const int tl = tid >> 1, h2 = tid & 1;
    const float* crow = smf + tl * 72 + h2 * 36;
    if (IN_HALF) {
        // out = f (fp32), relu(conv) + residual
        float* orow = (float*)out_v + ((size_t)b * TLEN + t0 + tl) * 64 + h2 * 32;
#pragma unroll
        for (int j = 0; j < 8; j++) {
            const float4 bv = __ldg((const float4*)bias + h2 * 8 + j);
            const float4 c = *(const float4*)(crow + j * 4);
            const float4 rr = __ldg((const float4*)orow + j);
            float4 v;
            v.x = fmaxf(c.x + bv.x, 0.f) + rr.x;
            v.y = fmaxf(c.y + bv.y, 0.f) + rr.y;
            v.z = fmaxf(c.z + bv.z, 0.f) + rr.z;
            v.w = fmaxf(c.w + bv.w, 0.f) + rr.w;
            ((float4*)orow)[j] = v;
        }
    } else {
        // out = h (fp16), relu(conv)
        __half* orow = (__half*)out_v + ((size_t)b * TLEN + t0 + tl) * 64 + h2 * 32;
#pragma unroll
        for (int j = 0; j < 8; j++) {
            const float4 bv = __ldg((const float4*)bias + h2 * 8 + j);
            const float4 c = *(const float4*)(crow + j * 4);
            uint2 u;
            u.x = h2pack(fmaxf(c.x + bv.x, 0.f), fmaxf(c.y + bv.y, 0.f));
            u.y = h2pack(fmaxf(c.z + bv.z, 0.f), fmaxf(c.w + bv.w, 0.f));
            ((uint2*)orow)[j] = u;
        }
    }
}

// ---------------------------------------------------------------------------
// Fused layer-0: one GEMM, N=128 = [ h-half (w0a, relu, fp16) | f-half (w0r 1x1) ].
// Input = virtual concat [x(15) ; emb(8) ; zeros(9)] = 32 padded channels, t-major x.
// CTA = 64-t tile x 128 N; K = 96 (3 taps x 2 kc16). 8 warps 2M x 4N (32t x 32o).
// A smem: 66 rows x 32 fp16, stride 80B.
// ---------------------------------------------------------------------------
#define CONV0_SMEM 18432   // 64*72*4 bounce (>= 66*80 A region)

__global__ void __launch_bounds__(256, 4) conv0_kernel(
    const float* __restrict__ x, const int* __restrict__ ids,
    const float* __restrict__ emb,
    const uint2* __restrict__ wp0,
    const float* __restrict__ b0a, const float* __restrict__ b0r,
    __half* __restrict__ hout, float* __restrict__ fout)
{
    extern __shared__ __align__(16) char smraw[];
    __half* smh = (__half*)smraw;
    float*  smf = (float*)smraw;
    const int tid = threadIdx.x;
    const int t0  = blockIdx.x * 64;
    const int b   = blockIdx.y;

    // ---- stage A: 66 rows x 32 padded ch ----
    const int id = __ldg(ids + b);
    for (int idx = tid; idx < 32 * 66; idx += 256) {
        const int ch = idx / 66, r = idx - ch * 66;
        const int t = t0 - 2 + r;
        float v = 0.f;
        if (t >= 0) {
            if (ch < 15)       v = __ldg(x + ((size_t)b * 15 + ch) * TLEN + t);
            else if (ch < 23)  v = __ldg(emb + id * 8 + (ch - 15));
        }
        smh[r * 40 + ch] = __float2half_rn(v);
    }
    __syncthreads();

    const int lane = tid & 31, wid = tid >> 5;
    const int warpM = wid & 1, warpN = wid >> 1;   // 2M x 4N
    const int g = lane >> 2, tg = lane & 3;

    const uint32_t a_base = smem_u32(smraw) +
        (warpM * 32 + (lane & 15)) * 80 + ((lane >> 4) << 4);
    const uint2* wl = wp0 + lane;

    float acc[2][4][4];
#pragma unroll
    for (int mf = 0; mf < 2; mf++)
#pragma unroll
        for (int nf = 0; nf < 4; nf++)
#pragma unroll
            for (int r = 0; r < 4; r++) acc[mf][nf][r] = 0.f;

#pragma unroll
    for (int kk = 0; kk < 6; kk++) {
        const int tap = kk >> 1, cc = kk & 1;
        uint32_t A0[4], A1[4];
        const uint32_t ad = a_base + tap * 80 + cc * 32;
        LDSM4(A0, ad);
        LDSM4(A1, ad + 16 * 80);
        const uint2* wk = wl + (kk * 16 + warpN * 4) * 32;
        const uint2 b0 = __ldg(wk);
        const uint2 b1 = __ldg(wk + 32);
        const uint2 b2 = __ldg(wk + 64);
        const uint2 b3 = __ldg(wk + 96);
        mma_f16(acc[0][0], A0, b0);
        mma_f16(acc[0][1], A0, b1);
        mma_f16(acc[0][2], A0, b2);
        mma_f16(acc[0][3], A0, b3);
        mma_f16(acc[1][0], A1, b0);
        mma_f16(acc[1][1], A1, b1);
        mma_f16(acc[1][2], A1, b2);
        mma_f16(acc[1][3], A1, b3);
    }
    __syncthreads();

    const int tl = tid >> 1, h2 = tid & 1;          // tl 0..127 (only <64 used)
    // ---- h half (warpN 0,1 -> o 0..63): relu -> fp16 ----
    if (warpN < 2) {
#pragma unroll
        for (int mf = 0; mf < 2; mf++)
#pragma unroll
            for (int nf = 0; nf < 4; nf++) {
                const int ro = warpM * 32 + mf * 16 + g;
                const int co = warpN * 36 + nf * 8 + tg * 2;
                smf[ro * 72 + co]           = acc[mf][nf][0];
                smf[ro * 72 + co + 1]       = acc[mf][nf][1];
                smf[(ro + 8) * 72 + co]     = acc[mf][nf][2];
                smf[(ro + 8) * 72 + co + 1] = acc[mf][nf][3];
            }
    }
    __syncthreads();
    if (tid < 128) {
        const float* crow = smf + tl * 72 + h2 * 36;
        __half* orow = hout + ((size_t)b * TLEN + t0 + tl) * 64 + h2 * 32;
#pragma unroll
        for (int j = 0; j < 8; j++) {
            const float4 bv = __ldg((const float4*)b0a + h2 * 8 + j);
            const float4 c = *(const float4*)(crow + j * 4);
            uint2 u;
            u.x = h2pack(fmaxf(c.x + bv.x, 0.f), fmaxf(c.y + bv.y, 0.f));
            u.y = h2pack(fmaxf(c.z + bv.z, 0.f), fmaxf(c.w + bv.w, 0.f));
            ((uint2*)orow)[j] = u;
        }
    }
    __syncthreads();
    // ---- f half (warpN 2,3 -> o 64..127): no relu -> fp32 ----
    if (warpN >= 2) {
#pragma unroll
        for (int mf = 0; mf < 2; mf++)
#pragma unroll
            for (int nf = 0; nf < 4; nf++) {
                const int ro = warpM * 32 + mf * 16 + g;
                const int co = (warpN - 2) * 36 + nf * 8 + tg * 2;
                smf[ro * 72 + co]           = acc[mf][nf][0];
                smf[ro * 72 + co + 1]       = acc[mf][nf][1];
                smf[(ro + 8) * 72 + co]     = acc[mf][nf][2];
                smf[(ro + 8) * 72 + co + 1] = acc[mf][nf][3];
            }
    }
    __syncthreads();
    if (tid < 128) {
        const float* crow = smf + tl * 72 + h2 * 36;
        float* orow = fout + ((size_t)b * TLEN + t0 + tl) * 64 + h2 * 32;
#pragma unroll
        for (int j = 0; j < 8; j++) {
            const float4 bv = __ldg((const float4*)b0r + h2 * 8 + j);
            float4 c = *(const float4*)(crow + j * 4);
            c.x += bv.x; c.y += bv.y; c.z += bv.z; c.w += bv.w;
            ((float4*)orow)[j] = c;
        }
    }
}

// ---------------------------------------------------------------------------
// Heads (f fp32, channels-last)
// ---------------------------------------------------------------------------
__device__ __forceinline__ float softplusf(float x) {
    if (x > 20.f) return x;
    return log1pf(expf(x));
}

__global__ void __launch_bounds__(256) head_kernel(
    const float* __restrict__ f,
    const float* __restrict__ pet_w, const float* __restrict__ pet_b,
    const float* __restrict__ pck_w, const float* __restrict__ pck_b,
    const float* __restrict__ aet_w, const float* __restrict__ aet_b,
    float* __restrict__ out)
{
    int g = blockIdx.x * blockDim.x + threadIdx.x;
    if (g >= BATCH * TLEN) return;
    const float* fb = f + (size_t)g * 64;

    float a0 = 0.f, a1 = 0.f, a2 = 0.f;
#pragma unroll
    for (int j = 0; j < 16; j++) {
        const float4 v  = __ldg((const float4*)fb + j);
        const float4 w0 = __ldg((const float4*)pet_w + j);
        const float4 w1 = __ldg((const float4*)pck_w + j);
        const float4 w2 = __ldg((const float4*)aet_w + j);
        a0 += v.x * w0.x + v.y * w0.y + v.z * w0.z + v.w * w0.w;
        a1 += v.x * w1.x + v.y * w1.y + v.z * w1.z + v.w * w1.w;
        a2 += v.x * w2.x + v.y * w2.y + v.z * w2.z + v.w * w2.w;
    }
    float pet = softplusf(a0 + __ldg(pet_b));
    float pck = softplusf(a1 + __ldg(pck_b));
    float z   = a2 + __ldg(aet_w + 64) * pet + __ldg(aet_w + 65) * pck + __ldg(aet_b);
    float aet = pet / (1.f + expf(-z));
    float cwd = pet - aet;

    const int N = BATCH * TLEN;
    out[g]         = pet;
    out[N + g]     = pck;
    out[2 * N + g] = aet;
    out[3 * N + g] = cwd;
}

// ===========================================================================
extern "C" void kernel_launch(void* const* d_in, const int* in_sizes, int n_in,
                              void* d_out, int out_size)
{
    const float* x     = (const float*)d_in[0];
    const int*   ids   = (const int*)  d_in[1];
    const float* emb   = (const float*)d_in[2];
    const float* w0a   = (const float*)d_in[3];
    const float* b0a   = (const float*)d_in[4];
    const float* w0b   = (const float*)d_in[5];
    const float* b0b   = (const float*)d_in[6];
    const float* w0r   = (const float*)d_in[7];
    const float* b0r   = (const float*)d_in[8];
    const float* wa    = (const float*)d_in[9];
    const float* ba    = (const float*)d_in[10];
    const float* wb    = (const float*)d_in[11];
    const float* bb    = (const float*)d_in[12];
    const float* pet_w = (const float*)d_in[13];
    const float* pet_b = (const float*)d_in[14];
    const float* pck_w = (const float*)d_in[15];
    const float* pck_b = (const float*)d_in[16];
    const float* aet_w = (const float*)d_in[17];
    const float* aet_b = (const float*)d_in[18];
    float* out = (float*)d_out;

    float* f; __half* h; uint2* wp;
    cudaGetSymbolAddress((void**)&f, g_f);
    cudaGetSymbolAddress((void**)&h, g_h);
    cudaGetSymbolAddress((void**)&wp, g_wp);

    // Repack all weights to fp16 fragments.
    repack_kernel<<<(10 * 3072 + 255) / 256, 256>>>(w0b, wa, wb, w0a, w0r);

    // Fused layer 0: h = relu(conv3(xin,w0a)) [fp16], f = conv1(xin,w0r) [fp32].
    conv0_kernel<<<dim3(16, BATCH), 256, CONV0_SMEM>>>(x, ids, emb, wp + 9 * 3072,
                                                       b0a, b0r, h, f);

    dim3 grid(TLEN / 128, BATCH);
    // f += relu(conv3(h, w0b))
    mconv_kernel<1,  true ><<<grid, 256, MCONV_SMEM>>>(h, f, wp + 0 * 3072, b0b);

    // Residual blocks d = 2, 4, 8, 16:
    mconv_kernel<2,  false><<<grid, 256, MCONV_SMEM>>>(f, h, wp + 1 * 3072, ba + 0 * NCH);
    mconv_kernel<2,  true ><<<grid, 256, MCONV_SMEM>>>(h, f, wp + 5 * 3072, bb + 0 * NCH);

    mconv_kernel<4,  false><<<grid, 256, MCONV_SMEM>>>(f, h, wp + 2 * 3072, ba + 1 * NCH);
    mconv_kernel<4,  true ><<<grid, 256, MCONV_SMEM>>>(h, f, wp + 6 * 3072, bb + 1 * NCH);

    mconv_kernel<8,  false><<<grid, 256, MCONV_SMEM>>>(f, h, wp + 3 * 3072, ba + 2 * NCH);
    mconv_kernel<8,  true ><<<grid, 256, MCONV_SMEM>>>(h, f, wp + 7 * 3072, bb + 2 * NCH);

    mconv_kernel<16, false><<<grid, 256, MCONV_SMEM>>>(f, h, wp + 4 * 3072, ba + 3 * NCH);
    mconv_kernel<16, true ><<<grid, 256, MCONV_SMEM>>>(h, f, wp + 8 * 3072, bb + 3 * NCH);

    head_kernel<<<(BATCH * TLEN + 255) / 256, 256>>>(f, pet_w, pet_b, pck_w, pck_b,
                                                     aet_w, aet_b, out);
}